// round 1
// baseline (speedup 1.0000x reference)
#include <cuda_runtime.h>
#include <utility>
#include <cstdint>

// ---------------------------------------------------------------------------
// Problem constants (fixed by reference: LS=[0,1,2], OFF=[0,1,4], 11 paths,
// MUL=32, BASE_DIM=9, N_NODES=10000)
// ---------------------------------------------------------------------------
#define BASE_DIM 9
#define MUL 32
#define NPATHS 11
#define MAX_NODES 10000
#define ROW (MUL * BASE_DIM) /* 288 */

struct BEntry { int i, j, k, p; };
struct BTable { BEntry e[96]; int n; };

// Compile-time enumeration of the structural nonzeros of the real-basis
// Wigner-3j blocks. Real SH selection rules (exact):
//   |m3| in { |m1|+|m2| , ||m1|-|m2|| }  (azimuthal Fourier matching)
//   count of negative-m (sin-type) components must be even.
constexpr BTable build_table() {
    constexpr int ls[3]  = {0, 1, 2};
    constexpr int off[3] = {0, 1, 4};
    constexpr int paths[NPATHS][3] = {
        {0,0,0},{1,1,0},{2,2,0},
        {0,1,1},{1,0,1},{1,2,1},{2,1,1},
        {0,2,2},{1,1,2},{2,0,2},{2,2,2}};
    BTable t{};
    t.n = 0;
    for (int p = 0; p < NPATHS; ++p) {
        const int la = ls[paths[p][0]], lb = ls[paths[p][1]], lc = ls[paths[p][2]];
        for (int m1 = -la; m1 <= la; ++m1)
        for (int m2 = -lb; m2 <= lb; ++m2)
        for (int m3 = -lc; m3 <= lc; ++m3) {
            const int a = m1 < 0 ? -m1 : m1;
            const int b = m2 < 0 ? -m2 : m2;
            const int c = m3 < 0 ? -m3 : m3;
            const int d = a > b ? a - b : b - a;
            if (c != a + b && c != d) continue;
            const int negs = (m1 < 0) + (m2 < 0) + (m3 < 0);
            if (negs & 1) continue;
            t.e[t.n].i = off[paths[p][0]] + la + m1;
            t.e[t.n].j = off[paths[p][1]] + lb + m2;
            t.e[t.n].k = off[paths[p][2]] + lc + m3;
            t.e[t.n].p = p;
            ++t.n;
        }
    }
    return t;
}

constexpr BTable TAB = build_table();
constexpr int NS = TAB.n;
static_assert(NS > 0 && NS <= 96, "table overflow");

// runtime copy for the table-build kernel (dynamic indexing there)
__constant__ BTable c_TAB = TAB;

// ---------------------------------------------------------------------------
// Device scratch (no allocations allowed)
// ---------------------------------------------------------------------------
__device__ __align__(16) float g_scatter[(size_t)MAX_NODES * ROW]; // 11.52 MB
__device__ float g_val[96 * MUL]; // weighted 3j values, layout [s][u]

// ---------------------------------------------------------------------------
// Kernel 1: zero the scatter buffer
// ---------------------------------------------------------------------------
__global__ void zero_kernel() {
    const int total = MAX_NODES * (ROW / 4);
    float4* p = reinterpret_cast<float4*>(g_scatter);
    for (int i = blockIdx.x * blockDim.x + threadIdx.x; i < total;
         i += gridDim.x * blockDim.x) {
        p[i] = make_float4(0.f, 0.f, 0.f, 0.f);
    }
}

// ---------------------------------------------------------------------------
// Kernel 2: scatter-add x2 rows into node rows (fp32 atomics / REDG)
// ---------------------------------------------------------------------------
__global__ void scatter_kernel(const float* __restrict__ x2,
                               const int* __restrict__ idxs, int E) {
    const int t = blockIdx.x * blockDim.x + threadIdx.x;
    const int total = E * (ROW / 4);
    if (t >= total) return;
    const int e = t / (ROW / 4);
    const int c = t - e * (ROW / 4);
    const int node = idxs[e];
    const float4 v = reinterpret_cast<const float4*>(x2)[t];
    float* dst = g_scatter + (size_t)node * ROW + c * 4;
    atomicAdd(dst + 0, v.x);
    atomicAdd(dst + 1, v.y);
    atomicAdd(dst + 2, v.z);
    atomicAdd(dst + 3, v.w);
}

// ---------------------------------------------------------------------------
// Kernel 3: build weighted sparse values  val[s][u] = weights[u][p_s] * w3j[p_s][i,j,k]
// ---------------------------------------------------------------------------
__global__ void tables_kernel(const float* __restrict__ w3j,
                              const float* __restrict__ weights) {
    const int t = blockIdx.x * blockDim.x + threadIdx.x;
    if (t >= NS * MUL) return;
    const int s = t >> 5;
    const int u = t & 31;
    const BEntry en = c_TAB.e[s];
    g_val[t] = weights[u * NPATHS + en.p] *
               w3j[en.p * 729 + en.i * 81 + en.j * 9 + en.k];
}

// ---------------------------------------------------------------------------
// Kernel 4: per-edge contraction. warp = edge, lane = u.
// All 83 terms fully unrolled with compile-time (i,j,k); values in registers.
// ---------------------------------------------------------------------------
template <int S_>
__device__ __forceinline__ void tp_term(float* acc, const float* a,
                                        const float* b, const float* v) {
    constexpr int i = TAB.e[S_].i;
    constexpr int j = TAB.e[S_].j;
    constexpr int k = TAB.e[S_].k;
    acc[k] = fmaf(a[i] * b[j], v[S_], acc[k]);
}

template <int... Ss>
__device__ __forceinline__ void tp_all(float* acc, const float* a,
                                       const float* b, const float* v,
                                       std::integer_sequence<int, Ss...>) {
    (tp_term<Ss>(acc, a, b, v), ...);
}

#define CWARPS 8

__global__ __launch_bounds__(CWARPS * 32)
void compute_kernel(const float* __restrict__ x1, const int* __restrict__ idxs,
                    float* __restrict__ out, int E, int totalWarps) {
    __shared__ float buf[CWARPS][ROW];
    const int lane = threadIdx.x & 31;
    const int wip  = threadIdx.x >> 5;
    const int gw   = blockIdx.x * CWARPS + wip;
    float* wbuf = buf[wip];

    // per-lane (= per-u) weighted 3j values, resident in registers
    float v[NS];
#pragma unroll
    for (int s = 0; s < NS; ++s) v[s] = g_val[s * 32 + lane];

    for (int e = gw; e < E; e += totalWarps) {
        const int node = idxs[e];

        // stage x1 row (coalesced) -> registers (conflict-free stride-9 LDS)
        const float* x1e = x1 + (size_t)e * ROW;
#pragma unroll
        for (int j = 0; j < 9; ++j) wbuf[j * 32 + lane] = x1e[j * 32 + lane];
        __syncwarp();
        float a[9];
#pragma unroll
        for (int i = 0; i < 9; ++i) a[i] = wbuf[lane * 9 + i];
        __syncwarp();

        // stage gathered x2_scatter row (L2-resident, coalesced)
        const float* x2n = g_scatter + (size_t)node * ROW;
#pragma unroll
        for (int j = 0; j < 9; ++j) wbuf[j * 32 + lane] = x2n[j * 32 + lane];
        __syncwarp();
        float b[9];
#pragma unroll
        for (int j = 0; j < 9; ++j) b[j] = wbuf[lane * 9 + j];
        __syncwarp();

        float acc[9] = {0.f, 0.f, 0.f, 0.f, 0.f, 0.f, 0.f, 0.f, 0.f};
        tp_all(acc, a, b, v, std::make_integer_sequence<int, NS>{});

        // transpose back through smem, coalesced store
#pragma unroll
        for (int k = 0; k < 9; ++k) wbuf[lane * 9 + k] = acc[k];
        __syncwarp();
        float* oute = out + (size_t)e * ROW;
#pragma unroll
        for (int j = 0; j < 9; ++j) oute[j * 32 + lane] = wbuf[j * 32 + lane];
        __syncwarp();
    }
}

// ---------------------------------------------------------------------------
// launch
// ---------------------------------------------------------------------------
extern "C" void kernel_launch(void* const* d_in, const int* in_sizes, int n_in,
                              void* d_out, int out_size) {
    const float* x1   = (const float*)d_in[0];
    const float* x2   = (const float*)d_in[1];
    const int*   idxs = (const int*)d_in[2];

    // locate w3j / weights robustly by element count (scalar input may or may
    // not be materialized)
    const float* w3j = nullptr;
    const float* weights = nullptr;
    for (int i = 3; i < n_in; ++i) {
        if (in_sizes[i] == NPATHS * 729) w3j = (const float*)d_in[i];
        else if (in_sizes[i] == MUL * NPATHS) weights = (const float*)d_in[i];
    }

    const int E = in_sizes[0] / ROW;
    float* out = (float*)d_out;

    zero_kernel<<<2048, 256>>>();
    scatter_kernel<<<(E * (ROW / 4) + 255) / 256, 256>>>(x2, idxs, E);
    tables_kernel<<<(NS * MUL + 255) / 256, 256>>>(w3j, weights);

    const int blocks = 1480;
    const int totalWarps = blocks * CWARPS;
    compute_kernel<<<blocks, CWARPS * 32>>>(x1, idxs, out, E, totalWarps);
}

// round 3
// speedup vs baseline: 1.6204x; 1.6204x over previous
#include <cuda_runtime.h>
#include <utility>
#include <cstdint>

// ---------------------------------------------------------------------------
// Problem constants (fixed: LS=[0,1,2], OFF=[0,1,4], 11 paths, MUL=32, dim=9)
// ---------------------------------------------------------------------------
#define BASE_DIM 9
#define MUL 32
#define NPATHS 11
#define MAX_NODES 10000
#define ROW (MUL * BASE_DIM) /* 288 */

struct BEntry { int i, j, k, p; };
struct BTable { BEntry e[96]; int n; };

// Compile-time enumeration of structural nonzeros of the real-basis Wigner-3j
// blocks (exact real-SH selection rules). Verified by R1 pass (rel_err 8e-8).
constexpr BTable build_table() {
    constexpr int ls[3]  = {0, 1, 2};
    constexpr int off[3] = {0, 1, 4};
    constexpr int paths[NPATHS][3] = {
        {0,0,0},{1,1,0},{2,2,0},
        {0,1,1},{1,0,1},{1,2,1},{2,1,1},
        {0,2,2},{1,1,2},{2,0,2},{2,2,2}};
    BTable t{};
    t.n = 0;
    for (int p = 0; p < NPATHS; ++p) {
        const int la = ls[paths[p][0]], lb = ls[paths[p][1]], lc = ls[paths[p][2]];
        for (int m1 = -la; m1 <= la; ++m1)
        for (int m2 = -lb; m2 <= lb; ++m2)
        for (int m3 = -lc; m3 <= lc; ++m3) {
            const int a = m1 < 0 ? -m1 : m1;
            const int b = m2 < 0 ? -m2 : m2;
            const int c = m3 < 0 ? -m3 : m3;
            const int d = a > b ? a - b : b - a;
            if (c != a + b && c != d) continue;
            const int negs = (m1 < 0) + (m2 < 0) + (m3 < 0);
            if (negs & 1) continue;
            t.e[t.n].i = off[paths[p][0]] + la + m1;
            t.e[t.n].j = off[paths[p][1]] + lb + m2;
            t.e[t.n].k = off[paths[p][2]] + lc + m3;
            t.e[t.n].p = p;
            ++t.n;
        }
    }
    return t;
}

constexpr BTable TAB = build_table();
constexpr int NS = TAB.n;
static_assert(NS == 83, "expected 83 structural nonzeros");

// Hoist path start offsets into a constexpr ARRAY (variable reads are legal in
// device code; host-constexpr function CALLS in device context are not).
struct PStarts { int v[NPATHS + 1]; };
constexpr PStarts build_pstarts() {
    PStarts r{};
    for (int p = 0; p <= NPATHS; ++p) {
        int c = 0;
        for (int s = 0; s < NS; ++s) if (TAB.e[s].p < p) ++c;
        r.v[p] = c;
    }
    return r;
}
constexpr PStarts PSTART = build_pstarts();

// output block base/count per path (out irrep: p0-2 -> l=0, p3-6 -> l=1, p7-10 -> l=2)
constexpr int PATH_K_BASE[NPATHS] = {0,0,0, 1,1,1,1, 4,4,4,4};
constexpr int PATH_K_CNT [NPATHS] = {1,1,1, 3,3,3,3, 5,5,5,5};

// runtime copy of table for the tiny prep kernel
__constant__ BTable c_TAB = TAB;
// lane-invariant raw w3j entry values (filled per-launch via D2D memcpy)
__constant__ float c_VAL[96];

// ---------------------------------------------------------------------------
// Device scratch (no allocations allowed)
// ---------------------------------------------------------------------------
__device__ __align__(16) float g_scatter[(size_t)MAX_NODES * ROW]; // 11.52 MB
__device__ float g_cval[96];

// ---------------------------------------------------------------------------
// Kernel 1: zero the scatter buffer
// ---------------------------------------------------------------------------
__global__ void zero_kernel() {
    const int total = MAX_NODES * (ROW / 4);
    float4* p = reinterpret_cast<float4*>(g_scatter);
    for (int i = blockIdx.x * blockDim.x + threadIdx.x; i < total;
         i += gridDim.x * blockDim.x) {
        p[i] = make_float4(0.f, 0.f, 0.f, 0.f);
    }
}

// ---------------------------------------------------------------------------
// Kernel 2: scatter-add x2 rows into node rows via 128-bit vector reductions
// ---------------------------------------------------------------------------
__global__ void scatter_kernel(const float* __restrict__ x2,
                               const int* __restrict__ idxs, int E) {
    const int t = blockIdx.x * blockDim.x + threadIdx.x;
    const int total = E * (ROW / 4);
    if (t >= total) return;
    const int e = t / (ROW / 4);
    const int c = t - e * (ROW / 4);
    const int node = idxs[e];
    const float4 v = reinterpret_cast<const float4*>(x2)[t];
    float* dst = g_scatter + (size_t)node * ROW + c * 4;
    asm volatile(
        "red.relaxed.gpu.global.add.v4.f32 [%0], {%1, %2, %3, %4};"
        :: "l"(__cvta_generic_to_global(dst)),
           "f"(v.x), "f"(v.y), "f"(v.z), "f"(v.w)
        : "memory");
}

// ---------------------------------------------------------------------------
// Kernel 3: extract raw w3j entry values (lane-invariant) into g_cval
// ---------------------------------------------------------------------------
__global__ void tables_kernel(const float* __restrict__ w3j) {
    const int s = threadIdx.x;
    if (s >= NS) { if (s < 96) g_cval[s] = 0.f; return; }
    const BEntry en = c_TAB.e[s];
    g_cval[s] = w3j[en.p * 729 + en.i * 81 + en.j * 9 + en.k];
}

// ---------------------------------------------------------------------------
// Contraction codegen: per-path, accumulate pacc_k = sum a_i*b_j*c_s (c_s from
// constant memory, compile-time index -> const-pipe load, zero GPR cost),
// then acc[k] += wp[p] * pacc_k  (wp per-lane, 11 regs).
// ---------------------------------------------------------------------------
template <int P, int S, int SEND>
__device__ __forceinline__ void path_entries(float* pacc, const float* a,
                                             const float* b) {
    if constexpr (S < SEND) {
        constexpr int i = TAB.e[S].i;
        constexpr int j = TAB.e[S].j;
        constexpr int kk = TAB.e[S].k - PATH_K_BASE[P];
        pacc[kk] = fmaf(a[i] * b[j], c_VAL[S], pacc[kk]);
        path_entries<P, S + 1, SEND>(pacc, a, b);
    }
}

template <int P>
__device__ __forceinline__ void do_path(float* acc, const float* a,
                                        const float* b, const float* wp) {
    constexpr int kb = PATH_K_BASE[P];
    constexpr int kc = PATH_K_CNT[P];
    float pacc[5] = {0.f, 0.f, 0.f, 0.f, 0.f};
    path_entries<P, PSTART.v[P], PSTART.v[P + 1]>(pacc, a, b);
#pragma unroll
    for (int kk = 0; kk < kc; ++kk)
        acc[kb + kk] = fmaf(wp[P], pacc[kk], acc[kb + kk]);
}

template <int... Ps>
__device__ __forceinline__ void do_all_paths(float* acc, const float* a,
                                             const float* b, const float* wp,
                                             std::integer_sequence<int, Ps...>) {
    (do_path<Ps>(acc, a, b, wp), ...);
}

// ---------------------------------------------------------------------------
// Kernel 4: per-edge contraction. warp = edge, lane = u (mul channel).
// ---------------------------------------------------------------------------
#define CWARPS 8

__global__ __launch_bounds__(CWARPS * 32, 4)
void compute_kernel(const float* __restrict__ x1, const int* __restrict__ idxs,
                    const float* __restrict__ weights, float* __restrict__ out,
                    int E, int totalWarps) {
    __shared__ float bufA[CWARPS][ROW];
    __shared__ float bufB[CWARPS][ROW];
    const int lane = threadIdx.x & 31;
    const int wip  = threadIdx.x >> 5;
    const int gw   = blockIdx.x * CWARPS + wip;
    float* bA = bufA[wip];
    float* bB = bufB[wip];
    float4* bA4 = reinterpret_cast<float4*>(bA);
    float4* bB4 = reinterpret_cast<float4*>(bB);

    // per-lane (= per-u) path weights, 11 registers
    float wp[NPATHS];
#pragma unroll
    for (int p = 0; p < NPATHS; ++p)
        wp[p] = __ldg(weights + lane * NPATHS + p);

    for (int e = gw; e < E; e += totalWarps) {
        const int node = __ldg(idxs + e);

        // issue all 6 (x1 + gather) 128-bit loads back-to-back for MLP
        const float4* p1 = reinterpret_cast<const float4*>(x1 + (size_t)e * ROW);
        const float4* p2 = reinterpret_cast<const float4*>(g_scatter + (size_t)node * ROW);
        float4 A0 = __ldg(p1 + lane);
        float4 A1 = __ldg(p1 + 32 + lane);
        float4 A2 = {};
        float4 B0 = __ldg(p2 + lane);
        float4 B1 = __ldg(p2 + 32 + lane);
        float4 B2 = {};
        if (lane < 8) {
            A2 = __ldg(p1 + 64 + lane);
            B2 = __ldg(p2 + 64 + lane);
        }
        bA4[lane] = A0; bA4[32 + lane] = A1;
        bB4[lane] = B0; bB4[32 + lane] = B1;
        if (lane < 8) { bA4[64 + lane] = A2; bB4[64 + lane] = B2; }
        __syncwarp();

        // transposed reads: stride-9 is conflict-free (gcd(9,32)=1)
        float a[9], b[9];
#pragma unroll
        for (int i = 0; i < 9; ++i) a[i] = bA[lane * 9 + i];
#pragma unroll
        for (int j = 0; j < 9; ++j) b[j] = bB[lane * 9 + j];
        __syncwarp();

        float acc[9] = {0.f,0.f,0.f,0.f,0.f,0.f,0.f,0.f,0.f};
        do_all_paths(acc, a, b, wp, std::make_integer_sequence<int, NPATHS>{});

        // transpose back through smem, 128-bit coalesced store
#pragma unroll
        for (int k = 0; k < 9; ++k) bA[lane * 9 + k] = acc[k];
        __syncwarp();
        float4* ov = reinterpret_cast<float4*>(out + (size_t)e * ROW);
        ov[lane] = bA4[lane];
        ov[32 + lane] = bA4[32 + lane];
        if (lane < 8) ov[64 + lane] = bA4[64 + lane];
        __syncwarp();
    }
}

// ---------------------------------------------------------------------------
// launch
// ---------------------------------------------------------------------------
extern "C" void kernel_launch(void* const* d_in, const int* in_sizes, int n_in,
                              void* d_out, int out_size) {
    const float* x1   = (const float*)d_in[0];
    const float* x2   = (const float*)d_in[1];
    const int*   idxs = (const int*)d_in[2];

    const float* w3j = nullptr;
    const float* weights = nullptr;
    for (int i = 3; i < n_in; ++i) {
        if (in_sizes[i] == NPATHS * 729) w3j = (const float*)d_in[i];
        else if (in_sizes[i] == MUL * NPATHS) weights = (const float*)d_in[i];
    }

    const int E = in_sizes[0] / ROW;
    float* out = (float*)d_out;

    zero_kernel<<<1024, 256>>>();
    scatter_kernel<<<(E * (ROW / 4) + 255) / 256, 256>>>(x2, idxs, E);
    tables_kernel<<<1, 96>>>(w3j);

    void* cval_dev = nullptr;
    cudaGetSymbolAddress(&cval_dev, g_cval);
    cudaMemcpyToSymbolAsync(c_VAL, cval_dev, 96 * sizeof(float), 0,
                            cudaMemcpyDeviceToDevice, 0);

    const int blocks = 592; // 148 SMs * 4 blocks
    const int totalWarps = blocks * CWARPS;
    compute_kernel<<<blocks, CWARPS * 32>>>(x1, idxs, weights, out, E, totalWarps);
}

// round 5
// speedup vs baseline: 1.7061x; 1.0529x over previous
#include <cuda_runtime.h>
#include <utility>
#include <cstdint>

// ---------------------------------------------------------------------------
// Problem constants (fixed: LS=[0,1,2], OFF=[0,1,4], 11 paths, MUL=32, dim=9)
// ---------------------------------------------------------------------------
#define BASE_DIM 9
#define MUL 32
#define NPATHS 11
#define MAX_NODES 10000
#define ROW (MUL * BASE_DIM) /* 288 */

struct BEntry { int i, j, k, p; };
struct BTable { BEntry e[96]; int n; };

// Compile-time enumeration of structural nonzeros of the real-basis Wigner-3j
// blocks (exact real-SH selection rules). Verified: rel_err ~8e-8.
constexpr BTable build_table() {
    constexpr int ls[3]  = {0, 1, 2};
    constexpr int off[3] = {0, 1, 4};
    constexpr int paths[NPATHS][3] = {
        {0,0,0},{1,1,0},{2,2,0},
        {0,1,1},{1,0,1},{1,2,1},{2,1,1},
        {0,2,2},{1,1,2},{2,0,2},{2,2,2}};
    BTable t{};
    t.n = 0;
    for (int p = 0; p < NPATHS; ++p) {
        const int la = ls[paths[p][0]], lb = ls[paths[p][1]], lc = ls[paths[p][2]];
        for (int m1 = -la; m1 <= la; ++m1)
        for (int m2 = -lb; m2 <= lb; ++m2)
        for (int m3 = -lc; m3 <= lc; ++m3) {
            const int a = m1 < 0 ? -m1 : m1;
            const int b = m2 < 0 ? -m2 : m2;
            const int c = m3 < 0 ? -m3 : m3;
            const int d = a > b ? a - b : b - a;
            if (c != a + b && c != d) continue;
            const int negs = (m1 < 0) + (m2 < 0) + (m3 < 0);
            if (negs & 1) continue;
            t.e[t.n].i = off[paths[p][0]] + la + m1;
            t.e[t.n].j = off[paths[p][1]] + lb + m2;
            t.e[t.n].k = off[paths[p][2]] + lc + m3;
            t.e[t.n].p = p;
            ++t.n;
        }
    }
    return t;
}

constexpr BTable TAB = build_table();
constexpr int NS = TAB.n;
static_assert(NS == 83, "expected 83 structural nonzeros");

// Path start offsets as a constexpr ARRAY (device-legal constexpr variable reads)
struct PStarts { int v[NPATHS + 1]; };
constexpr PStarts build_pstarts() {
    PStarts r{};
    for (int p = 0; p <= NPATHS; ++p) {
        int c = 0;
        for (int s = 0; s < NS; ++s) if (TAB.e[s].p < p) ++c;
        r.v[p] = c;
    }
    return r;
}
constexpr PStarts PSTART = build_pstarts();

// output block base/count per path (p0-2 -> k base 0, p3-6 -> 1, p7-10 -> 4)
constexpr int PATH_K_BASE[NPATHS] = {0,0,0, 1,1,1,1, 4,4,4,4};
constexpr int PATH_K_CNT [NPATHS] = {1,1,1, 3,3,3,3, 5,5,5,5};

__constant__ BTable c_TAB = TAB;
// lane-invariant raw w3j entry values (filled per-launch via D2D memcpy)
__constant__ float c_VAL[96];

// ---------------------------------------------------------------------------
// Device scratch (no allocations allowed)
// ---------------------------------------------------------------------------
__device__ __align__(16) float g_scatter[(size_t)MAX_NODES * ROW]; // 11.52 MB
__device__ float g_cval[96];

// ---------------------------------------------------------------------------
// Kernel 1: zero the scatter buffer; block 0 also extracts w3j entry values
// ---------------------------------------------------------------------------
__global__ void zero_tables_kernel(const float* __restrict__ w3j) {
    if (blockIdx.x == 0 && threadIdx.x < 96) {
        const int s = threadIdx.x;
        if (s < NS) {
            const BEntry en = c_TAB.e[s];
            g_cval[s] = w3j[en.p * 729 + en.i * 81 + en.j * 9 + en.k];
        } else {
            g_cval[s] = 0.f;
        }
    }
    const int total = MAX_NODES * (ROW / 4);
    float4* p = reinterpret_cast<float4*>(g_scatter);
    for (int i = blockIdx.x * blockDim.x + threadIdx.x; i < total;
         i += gridDim.x * blockDim.x) {
        p[i] = make_float4(0.f, 0.f, 0.f, 0.f);
    }
}

// ---------------------------------------------------------------------------
// Kernel 2: scatter-add x2 rows into node rows via 128-bit vector reductions
// ---------------------------------------------------------------------------
__global__ void scatter_kernel(const float* __restrict__ x2,
                               const int* __restrict__ idxs, int E) {
    const int t = blockIdx.x * blockDim.x + threadIdx.x;
    const int total = E * (ROW / 4);
    if (t >= total) return;
    const int e = t / (ROW / 4);
    const int c = t - e * (ROW / 4);
    const int node = idxs[e];
    const float4 v = reinterpret_cast<const float4*>(x2)[t];
    float* dst = g_scatter + (size_t)node * ROW + c * 4;
    asm volatile(
        "red.relaxed.gpu.global.add.v4.f32 [%0], {%1, %2, %3, %4};"
        :: "l"(__cvta_generic_to_global(dst)),
           "f"(v.x), "f"(v.y), "f"(v.z), "f"(v.w)
        : "memory");
}

// ---------------------------------------------------------------------------
// Contraction codegen. Entry values come from constant memory (compile-time
// indices, const pipe, zero GPR). Per-lane path weights come from shared mem.
// Output streamed per-irrep-group to cap accumulator live range at 5.
// ---------------------------------------------------------------------------
template <int P, int S, int SEND>
__device__ __forceinline__ void path_entries(float* pacc, const float* a,
                                             const float* b) {
    if constexpr (S < SEND) {
        constexpr int i = TAB.e[S].i;
        constexpr int j = TAB.e[S].j;
        constexpr int kk = TAB.e[S].k - PATH_K_BASE[P];
        pacc[kk] = fmaf(a[i] * b[j], c_VAL[S], pacc[kk]);
        path_entries<P, S + 1, SEND>(pacc, a, b);
    }
}

template <int P>
__device__ __forceinline__ void do_path(float* acc, const float* a,
                                        const float* b,
                                        const float* __restrict__ wsm,
                                        int lane) {
    constexpr int kc = PATH_K_CNT[P];
    float pacc[5] = {0.f, 0.f, 0.f, 0.f, 0.f};
    path_entries<P, PSTART.v[P], PSTART.v[P + 1]>(pacc, a, b);
    const float w = wsm[P * 32 + lane];
#pragma unroll
    for (int kk = 0; kk < kc; ++kk)
        acc[kk] = fmaf(w, pacc[kk], acc[kk]);
}

// ---------------------------------------------------------------------------
// Kernel 3: per-edge contraction. warp = edge, lane = u (mul channel).
// ---------------------------------------------------------------------------
#define CWARPS 8

__global__ __launch_bounds__(CWARPS * 32, 5)
void compute_kernel(const float* __restrict__ x1, const int* __restrict__ idxs,
                    const float* __restrict__ weights, float* __restrict__ out,
                    int E, int totalWarps) {
    __shared__ float bufA[CWARPS][ROW];
    __shared__ float bufB[CWARPS][ROW];
    __shared__ float wsm[NPATHS * 32]; // [p][u]
    const int lane = threadIdx.x & 31;
    const int wip  = threadIdx.x >> 5;
    const int gw   = blockIdx.x * CWARPS + wip;
    float* bA = bufA[wip];
    float* bB = bufB[wip];
    float4* bA4 = reinterpret_cast<float4*>(bA);
    float4* bB4 = reinterpret_cast<float4*>(bB);

    // stage per-lane path weights into shared memory once per block
    // (NPATHS*32 = 352 > blockDim = 256, so must stride — R4's bug)
    for (int t = threadIdx.x; t < NPATHS * 32; t += CWARPS * 32) {
        const int p = t >> 5;
        const int u = t & 31;
        wsm[t] = weights[u * NPATHS + p];
    }
    __syncthreads();

    for (int e = gw; e < E; e += totalWarps) {
        const int node = __ldg(idxs + e);

        // issue all 6 (x1 + gather) 128-bit loads back-to-back for MLP
        const float4* p1 = reinterpret_cast<const float4*>(x1 + (size_t)e * ROW);
        const float4* p2 = reinterpret_cast<const float4*>(g_scatter + (size_t)node * ROW);
        float4 A0 = __ldg(p1 + lane);
        float4 A1 = __ldg(p1 + 32 + lane);
        float4 A2 = {};
        float4 B0 = __ldg(p2 + lane);
        float4 B1 = __ldg(p2 + 32 + lane);
        float4 B2 = {};
        if (lane < 8) {
            A2 = __ldg(p1 + 64 + lane);
            B2 = __ldg(p2 + 64 + lane);
        }
        bA4[lane] = A0; bA4[32 + lane] = A1;
        bB4[lane] = B0; bB4[32 + lane] = B1;
        if (lane < 8) { bA4[64 + lane] = A2; bB4[64 + lane] = B2; }
        __syncwarp();

        // transposed reads: stride-9 is conflict-free (gcd(9,32)=1)
        float a[9], b[9];
#pragma unroll
        for (int i = 0; i < 9; ++i) a[i] = bA[lane * 9 + i];
#pragma unroll
        for (int j = 0; j < 9; ++j) b[j] = bB[lane * 9 + j];
        __syncwarp();

        // group 1: output l=0 (k=0), paths 0..2
        {
            float acc[1] = {0.f};
            do_path<0>(acc, a, b, wsm, lane);
            do_path<1>(acc, a, b, wsm, lane);
            do_path<2>(acc, a, b, wsm, lane);
            bA[lane * 9 + 0] = acc[0];
        }
        // group 2: output l=1 (k=1..3), paths 3..6
        {
            float acc[3] = {0.f, 0.f, 0.f};
            do_path<3>(acc, a, b, wsm, lane);
            do_path<4>(acc, a, b, wsm, lane);
            do_path<5>(acc, a, b, wsm, lane);
            do_path<6>(acc, a, b, wsm, lane);
#pragma unroll
            for (int kk = 0; kk < 3; ++kk) bA[lane * 9 + 1 + kk] = acc[kk];
        }
        // group 3: output l=2 (k=4..8), paths 7..10
        {
            float acc[5] = {0.f, 0.f, 0.f, 0.f, 0.f};
            do_path<7>(acc, a, b, wsm, lane);
            do_path<8>(acc, a, b, wsm, lane);
            do_path<9>(acc, a, b, wsm, lane);
            do_path<10>(acc, a, b, wsm, lane);
#pragma unroll
            for (int kk = 0; kk < 5; ++kk) bA[lane * 9 + 4 + kk] = acc[kk];
        }
        __syncwarp();

        // 128-bit coalesced writeback
        float4* ov = reinterpret_cast<float4*>(out + (size_t)e * ROW);
        ov[lane] = bA4[lane];
        ov[32 + lane] = bA4[32 + lane];
        if (lane < 8) ov[64 + lane] = bA4[64 + lane];
        __syncwarp();
    }
}

// ---------------------------------------------------------------------------
// launch
// ---------------------------------------------------------------------------
extern "C" void kernel_launch(void* const* d_in, const int* in_sizes, int n_in,
                              void* d_out, int out_size) {
    const float* x1   = (const float*)d_in[0];
    const float* x2   = (const float*)d_in[1];
    const int*   idxs = (const int*)d_in[2];

    const float* w3j = nullptr;
    const float* weights = nullptr;
    for (int i = 3; i < n_in; ++i) {
        if (in_sizes[i] == NPATHS * 729) w3j = (const float*)d_in[i];
        else if (in_sizes[i] == MUL * NPATHS) weights = (const float*)d_in[i];
    }

    const int E = in_sizes[0] / ROW;
    float* out = (float*)d_out;

    zero_tables_kernel<<<1024, 256>>>(w3j);
    scatter_kernel<<<(E * (ROW / 4) + 255) / 256, 256>>>(x2, idxs, E);

    void* cval_dev = nullptr;
    cudaGetSymbolAddress(&cval_dev, g_cval);
    cudaMemcpyToSymbolAsync(c_VAL, cval_dev, 96 * sizeof(float), 0,
                            cudaMemcpyDeviceToDevice, 0);

    const int blocks = 740; // 148 SMs * 5 blocks
    const int totalWarps = blocks * CWARPS;
    compute_kernel<<<blocks, CWARPS * 32>>>(x1, idxs, weights, out, E, totalWarps);
}